// round 2
// baseline (speedup 1.0000x reference)
#include <cuda_runtime.h>
#include <cuda_bf16.h>
#include <math.h>

// Problem dims
#define T_DIM 128
#define B_DIM 256
#define OBS_DIM 1024
#define PS 512          // PUBL_SPLIT
#define HID 512
#define GDIM 2048       // 4*HID
#define ACT 21
#define M_ROWS (T_DIM * B_DIM)   // 32768

// ---------------- scratch (device globals; no allocations allowed) -------------
__device__ float g_priv1[M_ROWS * HID];   // 64 MB
__device__ float g_priv2[M_ROWS * HID];   // 64 MB
__device__ float g_publx[M_ROWS * HID];   // 64 MB
__device__ float g_xg[M_ROWS * GDIM];     // 256 MB
__device__ float g_h[M_ROWS * HID];       // 64 MB  (publ_o, i.e. h at every t)
__device__ float g_c[B_DIM * HID];        // c state

// dones read as 32-bit words: nonzero <=> True. Works for both int32 (1) and
// float32 (1.0f = 0x3f800000) harness encodings of the bool array.
#define DONE(p, idx) (((const unsigned int*)(p))[idx] != 0u)

// ---------------- generic SGEMM: C = act(A @ W + bias) -------------------------
// Tiles: BM=128, BN=128, BK=16, 256 threads, 8x8 microtile.
__global__ __launch_bounds__(256) void gemm128(
    const float* __restrict__ A, int lda,
    const float* __restrict__ W,   // K x N row-major
    int N, int K,
    const float* __restrict__ bias,
    float* __restrict__ C,
    int relu)
{
    __shared__ float As[16][132];   // stored transposed: As[k][row]
    __shared__ float Bs[16][132];

    const int tid = threadIdx.x;
    const int tx = tid & 15;        // 0..15 -> 8 output cols each
    const int ty = tid >> 4;        // 0..15 -> 8 output rows each
    const int row0 = blockIdx.y * 128;
    const int col0 = blockIdx.x * 128;

    float acc[8][8];
#pragma unroll
    for (int i = 0; i < 8; i++)
#pragma unroll
        for (int j = 0; j < 8; j++) acc[i][j] = 0.f;

    for (int k0 = 0; k0 < K; k0 += 16) {
        // load A tile (128 rows x 16 k), transposed into As[k][row]
#pragma unroll
        for (int i = 0; i < 8; i++) {
            int idx = i * 256 + tid;
            int r = idx >> 4, kk = idx & 15;
            As[kk][r] = A[(size_t)(row0 + r) * lda + (k0 + kk)];
        }
        // load W tile (16 k x 128 cols)
#pragma unroll
        for (int i = 0; i < 8; i++) {
            int idx = i * 256 + tid;
            int kk = idx >> 7, c = idx & 127;
            Bs[kk][c] = W[(size_t)(k0 + kk) * N + (col0 + c)];
        }
        __syncthreads();

#pragma unroll
        for (int kk = 0; kk < 16; kk++) {
            float a[8], b[8];
            float4 a0 = *(const float4*)&As[kk][ty * 8];
            float4 a1 = *(const float4*)&As[kk][ty * 8 + 4];
            float4 b0 = *(const float4*)&Bs[kk][tx * 8];
            float4 b1 = *(const float4*)&Bs[kk][tx * 8 + 4];
            a[0]=a0.x; a[1]=a0.y; a[2]=a0.z; a[3]=a0.w;
            a[4]=a1.x; a[5]=a1.y; a[6]=a1.z; a[7]=a1.w;
            b[0]=b0.x; b[1]=b0.y; b[2]=b0.z; b[3]=b0.w;
            b[4]=b1.x; b[5]=b1.y; b[6]=b1.z; b[7]=b1.w;
#pragma unroll
            for (int i = 0; i < 8; i++)
#pragma unroll
                for (int j = 0; j < 8; j++)
                    acc[i][j] += a[i] * b[j];
        }
        __syncthreads();
    }

#pragma unroll
    for (int i = 0; i < 8; i++) {
        int r = row0 + ty * 8 + i;
#pragma unroll
        for (int j = 0; j < 8; j++) {
            int cc = col0 + tx * 8 + j;
            float v = acc[i][j];
            if (bias) v += bias[cc];
            if (relu) v = fmaxf(v, 0.f);
            C[(size_t)r * N + cc] = v;
        }
    }
}

// ---------------- LSTM step --------------------------------------------------
// gates[b][g*512+hid] = xg + (mask(h_prev) @ Wh) + b_lstm ; fused nonlinearity +
// c/h update in epilogue. CTA tile: 32 batch x 32 hid x 4 gates; grid (16, 8).
__global__ __launch_bounds__(128) void lstm_step(
    const float* __restrict__ Wh,        // [512][2048]
    const float* __restrict__ xg,        // [B][2048] slice for this t
    const float* __restrict__ blstm,     // [2048]
    const void* __restrict__ dn,         // [B] bool as 32-bit words
    const float* __restrict__ hprev,     // [B][512]
    float* __restrict__ cst,             // [B][512]
    float* __restrict__ hout)            // [B][512]
{
    __shared__ float Hs[32][33];         // [batch][k]
    __shared__ float Ws[32][128];        // [k][4 gates x 32 hid]

    const int tid = threadIdx.x;
    const int tx = tid & 31;             // hid within block
    const int ty = tid >> 5;             // 0..3 -> 8 batch rows each
    const int n0 = blockIdx.x * 32;      // hid block
    const int b0 = blockIdx.y * 32;      // batch block

    float acc[8][4];
#pragma unroll
    for (int i = 0; i < 8; i++)
#pragma unroll
        for (int g = 0; g < 4; g++) acc[i][g] = 0.f;

    for (int k0 = 0; k0 < HID; k0 += 32) {
        // h tile (masked by dones)
#pragma unroll
        for (int i = 0; i < 8; i++) {
            int idx = i * 128 + tid;
            int r = idx >> 5, kk = idx & 31;
            int b = b0 + r;
            float hv = hprev[(size_t)b * HID + k0 + kk];
            Hs[r][kk] = DONE(dn, b) ? 0.f : hv;
        }
        // W tile: column c (0..127) -> gate g=c>>5, hid n0+(c&31)
#pragma unroll
        for (int i = 0; i < 32; i++) {
            Ws[i][tid] = Wh[(size_t)(k0 + i) * GDIM + (tid >> 5) * HID + n0 + (tid & 31)];
        }
        __syncthreads();

#pragma unroll
        for (int kk = 0; kk < 32; kk++) {
            float w0 = Ws[kk][tx];
            float w1 = Ws[kk][32 + tx];
            float w2 = Ws[kk][64 + tx];
            float w3 = Ws[kk][96 + tx];
#pragma unroll
            for (int i = 0; i < 8; i++) {
                float a = Hs[ty * 8 + i][kk];
                acc[i][0] += a * w0;
                acc[i][1] += a * w1;
                acc[i][2] += a * w2;
                acc[i][3] += a * w3;
            }
        }
        __syncthreads();
    }

    const int hid = n0 + tx;
#pragma unroll
    for (int i = 0; i < 8; i++) {
        int b = b0 + ty * 8 + i;
        const float* xgb = xg + (size_t)b * GDIM;
        float ii = acc[i][0] + xgb[hid]          + blstm[hid];
        float ff = acc[i][1] + xgb[HID + hid]    + blstm[HID + hid];
        float gg = acc[i][2] + xgb[2*HID + hid]  + blstm[2*HID + hid];
        float oo = acc[i][3] + xgb[3*HID + hid]  + blstm[3*HID + hid];
        float is = 1.f / (1.f + expf(-ii));
        float fs = 1.f / (1.f + expf(-ff));
        float os = 1.f / (1.f + expf(-oo));
        float gt = tanhf(gg);
        float cm = DONE(dn, b) ? 0.f : cst[(size_t)b * HID + hid];
        float nc = fs * cm + is * gt;
        float nh = os * tanhf(nc);
        cst[(size_t)b * HID + hid] = nc;
        hout[(size_t)b * HID + hid] = nh;
    }
}

// ---------------- head: q = (o@Wv + bv) + (o@Wa + ba), o = priv_o * publ_o ----
__global__ __launch_bounds__(128) void head_kernel(
    const float* __restrict__ privo, const float* __restrict__ hbuf,
    const float* __restrict__ Wv, const float* __restrict__ bv,
    const float* __restrict__ Wa, const float* __restrict__ ba,
    float* __restrict__ outq)            // already offset to q region
{
    __shared__ float o[HID];
    const int row = blockIdx.x;          // 0..32767  (t*B + b)
    const int tid = threadIdx.x;
    for (int i = tid; i < HID; i += 128)
        o[i] = privo[(size_t)row * HID + i] * hbuf[(size_t)row * HID + i];
    __syncthreads();

    const int w = tid >> 5, lane = tid & 31;
    // value dot (computed redundantly per warp; cheap)
    float v = 0.f;
    for (int k = lane; k < HID; k += 32) v += o[k] * Wv[k];
#pragma unroll
    for (int off = 16; off > 0; off >>= 1) v += __shfl_down_sync(0xffffffffu, v, off);
    v = __shfl_sync(0xffffffffu, v, 0);

    for (int j = w; j < ACT; j += 4) {
        float s = 0.f;
        for (int k = lane; k < HID; k += 32) s += o[k] * Wa[k * ACT + j];
#pragma unroll
        for (int off = 16; off > 0; off >>= 1) s += __shfl_down_sync(0xffffffffu, s, off);
        if (lane == 0)
            outq[(size_t)row * ACT + j] = v + bv[0] + s + ba[j];
    }
}

__global__ void init_c_kernel(const float* __restrict__ c0, float* __restrict__ c)
{
    int i = blockIdx.x * blockDim.x + threadIdx.x;
    if (i < B_DIM * HID) c[i] = c0[i];
}

__global__ void tail_copy_kernel(const float* __restrict__ c,
                                 const float* __restrict__ hT,
                                 float* __restrict__ out)
{
    int i = blockIdx.x * blockDim.x + threadIdx.x;
    if (i < B_DIM * HID) {
        out[i] = c[i];                     // cT
        out[B_DIM * HID + i] = hT[i];      // hT
    }
}

// -----------------------------------------------------------------------------
extern "C" void kernel_launch(void* const* d_in, const int* in_sizes, int n_in,
                              void* d_out, int out_size)
{
    const float* c0    = (const float*)d_in[0];
    const float* h0    = (const float*)d_in[1];
    const float* obs   = (const float*)d_in[2];
    const void*  dones = d_in[3];
    const float* Wp1   = (const float*)d_in[4];
    const float* bp1   = (const float*)d_in[5];
    const float* Wp2   = (const float*)d_in[6];
    const float* bp2   = (const float*)d_in[7];
    const float* Wp3   = (const float*)d_in[8];
    const float* bp3   = (const float*)d_in[9];
    const float* Wpub  = (const float*)d_in[10];
    const float* bpub  = (const float*)d_in[11];
    const float* Wi    = (const float*)d_in[12];
    const float* Wh    = (const float*)d_in[13];
    const float* blstm = (const float*)d_in[14];
    const float* Wv    = (const float*)d_in[15];
    const float* bv    = (const float*)d_in[16];
    const float* Wa    = (const float*)d_in[17];
    const float* ba    = (const float*)d_in[18];
    float* out = (float*)d_out;

    float *priv1, *priv2, *publx, *xg, *hbuf, *cst;
    cudaGetSymbolAddress((void**)&priv1, g_priv1);
    cudaGetSymbolAddress((void**)&priv2, g_priv2);
    cudaGetSymbolAddress((void**)&publx, g_publx);
    cudaGetSymbolAddress((void**)&xg,    g_xg);
    cudaGetSymbolAddress((void**)&hbuf,  g_h);
    cudaGetSymbolAddress((void**)&cst,   g_c);

    dim3 blk(256);
    dim3 grid512(HID / 128, M_ROWS / 128);    // (4, 256)
    dim3 grid2048(GDIM / 128, M_ROWS / 128);  // (16, 256)

    // private path: 3 relu layers
    gemm128<<<grid512, blk>>>(obs,       OBS_DIM, Wp1, HID, PS,  bp1, priv1, 1);
    gemm128<<<grid512, blk>>>(priv1,     HID,     Wp2, HID, HID, bp2, priv2, 1);
    gemm128<<<grid512, blk>>>(priv2,     HID,     Wp3, HID, HID, bp3, priv1, 1);
    // public path + input gates
    gemm128<<<grid512, blk>>>(obs + PS,  OBS_DIM, Wpub, HID, OBS_DIM - PS, bpub, publx, 1);
    gemm128<<<grid2048, blk>>>(publx,    HID,     Wi,  GDIM, HID, nullptr, xg, 0);

    // LSTM scan
    init_c_kernel<<<(B_DIM * HID + 255) / 256, 256>>>(c0, cst);
    dim3 lgrid(HID / 32, B_DIM / 32);   // (16, 8)
    for (int t = 0; t < T_DIM; t++) {
        const float* hp = (t == 0) ? h0 : (hbuf + (size_t)(t - 1) * B_DIM * HID);
        lstm_step<<<lgrid, 128>>>(Wh,
                                  xg + (size_t)t * B_DIM * GDIM,
                                  blstm,
                                  (const void*)((const char*)dones + (size_t)t * B_DIM * 4),
                                  hp, cst,
                                  hbuf + (size_t)t * B_DIM * HID);
    }

    // Output layout: if out_size covers [cT, hT, q], q goes after the states;
    // if the harness only checks q, write it at offset 0.
    const int STATE = B_DIM * HID;                 // 131072
    const int QSZ   = M_ROWS * ACT;                // 688128
    float* qdst = out;
    int write_states = 0;
    if (out_size >= 2 * STATE + QSZ) { qdst = out + 2 * STATE; write_states = 1; }

    head_kernel<<<M_ROWS, 128>>>(priv1, hbuf, Wv, bv, Wa, ba, qdst);

    if (write_states) {
        tail_copy_kernel<<<(STATE + 255) / 256, 256>>>(
            cst, hbuf + (size_t)(T_DIM - 1) * B_DIM * HID, out);
    }
}

// round 5
// speedup vs baseline: 1.5423x; 1.5423x over previous
#include <cuda_runtime.h>
#include <cuda_bf16.h>
#include <math.h>

// Problem dims
#define T_DIM 128
#define B_DIM 256
#define OBS_DIM 1024
#define PS 512
#define HID 512
#define GDIM 2048
#define ACT 21
#define M_ROWS (T_DIM * B_DIM)   // 32768

// ---------------- scratch ------------------------------------------------------
__device__ float g_priv1[M_ROWS * HID];   // priv_o (final, persists through head)
__device__ float g_tmp[M_ROWS * HID];     // priv intermediate / publx
__device__ float g_publx[M_ROWS * HID];   // publ_x
__device__ float g_xg[M_ROWS * GDIM];     // x_gates
__device__ float g_h[M_ROWS * HID];       // h at every t
__device__ float g_c[B_DIM * HID];        // c state
__device__ float g_gates[B_DIM * GDIM];   // per-step gates buffer

// dones as 32-bit words: nonzero <=> True (works for int32 and float32 bools)
#define DONE(p, idx) (((const unsigned int*)(p))[idx] != 0u)

// ---------------- tf32 mma helpers --------------------------------------------
__device__ __forceinline__ unsigned f2tf32(float x) {
    unsigned u;
    asm("cvt.rna.tf32.f32 %0, %1;" : "=r"(u) : "f"(x));
    return u;
}

__device__ __forceinline__ void mma_tf32(float* d, const unsigned* a, const unsigned* b) {
    asm volatile(
        "mma.sync.aligned.m16n8k8.row.col.f32.tf32.tf32.f32 "
        "{%0,%1,%2,%3}, {%4,%5,%6,%7}, {%8,%9}, {%0,%1,%2,%3};"
        : "+f"(d[0]), "+f"(d[1]), "+f"(d[2]), "+f"(d[3])
        : "r"(a[0]), "r"(a[1]), "r"(a[2]), "r"(a[3]),
          "r"(b[0]), "r"(b[1]));
}

// ---------------- tf32 GEMM: C = act(A @ W + bias) -----------------------------
// BM=128, BN=128, BK=32. 256 threads = 8 warps (2 m x 4 n), warp tile 64x32.
#define BM 128
#define BN 128
#define BK 32

__global__ __launch_bounds__(256) void gemm_tf32(
    const float* __restrict__ A, int lda,
    const float* __restrict__ W,      // K x N row-major
    int N, int K,
    const float* __restrict__ bias,
    float* __restrict__ C,
    int relu,
    const void* __restrict__ dmask)   // optional row mask (32-bit bools)
{
    __shared__ unsigned As[BM][36];   // [m][k], pad 36 -> bank = (4m + k) % 32
    __shared__ unsigned Bs[BN][36];   // [n][k], pad 36 -> bank = (4n + k) % 32

    const int tid  = threadIdx.x;
    const int warp = tid >> 5;
    const int lane = tid & 31;
    const int wm = warp >> 2;         // 0..1
    const int wn = warp & 3;          // 0..3
    const int row0 = blockIdx.y * BM;
    const int col0 = blockIdx.x * BN;
    const int q = lane >> 2;          // 0..7
    const int r = lane & 3;           // 0..3

    float acc[4][4][4];
#pragma unroll
    for (int mt = 0; mt < 4; mt++)
#pragma unroll
        for (int nt = 0; nt < 4; nt++)
#pragma unroll
            for (int e = 0; e < 4; e++) acc[mt][nt][e] = 0.f;

    for (int k0 = 0; k0 < K; k0 += BK) {
        // A tile: 128 x 32, one float4 per thread x4, conflict-free STS.128
#pragma unroll
        for (int i = 0; i < 4; i++) {
            int lin = i * 256 + tid;
            int m   = lin >> 3;
            int k4  = (lin & 7) * 4;
            float4 v = *(const float4*)(A + (size_t)(row0 + m) * lda + k0 + k4);
            if (dmask && DONE(dmask, row0 + m)) v = make_float4(0.f, 0.f, 0.f, 0.f);
            As[m][k4 + 0] = f2tf32(v.x);
            As[m][k4 + 1] = f2tf32(v.y);
            As[m][k4 + 2] = f2tf32(v.z);
            As[m][k4 + 3] = f2tf32(v.w);
        }
        // B tile: 32 x 128 of W, stored transposed [n][k].
        // Per warp-instruction: 4k x 8n block -> 4 full 32B sectors in gmem,
        // conflict-free scalar stores in smem (banks 4n+k distinct).
#pragma unroll
        for (int i = 0; i < 16; i++) {
            int idx = i * 8 + warp;
            int k = (idx & 7) * 4 + r;
            int n = (idx >> 3) * 8 + q;
            Bs[n][k] = f2tf32(W[(size_t)(k0 + k) * N + col0 + n]);
        }
        __syncthreads();

#pragma unroll
        for (int ks = 0; ks < 4; ks++) {
            unsigned af[4][4], bf[4][2];
            int c = ks * 8 + r;
#pragma unroll
            for (int mt = 0; mt < 4; mt++) {
                int rr = wm * 64 + mt * 16 + q;
                af[mt][0] = As[rr][c];
                af[mt][1] = As[rr + 8][c];
                af[mt][2] = As[rr][c + 4];
                af[mt][3] = As[rr + 8][c + 4];
            }
#pragma unroll
            for (int nt = 0; nt < 4; nt++) {
                int nn = wn * 32 + nt * 8 + q;
                bf[nt][0] = Bs[nn][c];
                bf[nt][1] = Bs[nn][c + 4];
            }
#pragma unroll
            for (int mt = 0; mt < 4; mt++)
#pragma unroll
                for (int nt = 0; nt < 4; nt++)
                    mma_tf32(acc[mt][nt], af[mt], bf[nt]);
        }
        __syncthreads();
    }

#pragma unroll
    for (int mt = 0; mt < 4; mt++) {
        int rbase = row0 + wm * 64 + mt * 16 + q;
#pragma unroll
        for (int nt = 0; nt < 4; nt++) {
            int cbase = col0 + wn * 32 + nt * 8 + 2 * r;
            float v0 = acc[mt][nt][0];
            float v1 = acc[mt][nt][1];
            float v2 = acc[mt][nt][2];
            float v3 = acc[mt][nt][3];
            if (bias) {
                float b0 = bias[cbase], b1 = bias[cbase + 1];
                v0 += b0; v1 += b1; v2 += b0; v3 += b1;
            }
            if (relu) {
                v0 = fmaxf(v0, 0.f); v1 = fmaxf(v1, 0.f);
                v2 = fmaxf(v2, 0.f); v3 = fmaxf(v3, 0.f);
            }
            C[(size_t)rbase * N + cbase]           = v0;
            C[(size_t)rbase * N + cbase + 1]       = v1;
            C[(size_t)(rbase + 8) * N + cbase]     = v2;
            C[(size_t)(rbase + 8) * N + cbase + 1] = v3;
        }
    }
}

// ---------------- LSTM epilogue ------------------------------------------------
__global__ __launch_bounds__(256) void lstm_epilogue(
    const float* __restrict__ gates,   // [B][2048]
    const float* __restrict__ xg,      // [B][2048] slice for this t
    const float* __restrict__ blstm,   // [2048]
    const void* __restrict__ dn,       // [B] bool words for this t
    const float* __restrict__ cin,
    float* __restrict__ cout,
    float* __restrict__ hout)
{
    int idx = blockIdx.x * blockDim.x + threadIdx.x;   // 0..131071
    int b = idx >> 9, hid = idx & 511;
    size_t base = (size_t)b * GDIM;
    float ii = gates[base + hid]           + xg[base + hid]           + blstm[hid];
    float ff = gates[base + HID + hid]     + xg[base + HID + hid]     + blstm[HID + hid];
    float gg = gates[base + 2*HID + hid]   + xg[base + 2*HID + hid]   + blstm[2*HID + hid];
    float oo = gates[base + 3*HID + hid]   + xg[base + 3*HID + hid]   + blstm[3*HID + hid];
    float is = 1.f / (1.f + expf(-ii));
    float fs = 1.f / (1.f + expf(-ff));
    float os = 1.f / (1.f + expf(-oo));
    float gt = tanhf(gg);
    float cm = DONE(dn, b) ? 0.f : cin[(size_t)b * HID + hid];
    float nc = fs * cm + is * gt;
    cout[(size_t)b * HID + hid] = nc;
    hout[(size_t)b * HID + hid] = os * tanhf(nc);
}

// ---------------- head ---------------------------------------------------------
__global__ __launch_bounds__(256) void head_kernel(
    const float* __restrict__ privo, const float* __restrict__ hbuf,
    const float* __restrict__ Wv, const float* __restrict__ bv,
    const float* __restrict__ Wa, const float* __restrict__ ba,
    float* __restrict__ outq)
{
    __shared__ float so[8][HID];
    const int tid = threadIdx.x;
    const int w = tid >> 5, lane = tid & 31;
    const int row = blockIdx.x * 8 + w;

    for (int k = lane; k < HID; k += 32)
        so[w][k] = privo[(size_t)row * HID + k] * hbuf[(size_t)row * HID + k];
    __syncwarp();

    float acc = 0.f;
    if (lane < 21) {
        for (int k = 0; k < HID; k++)
            acc += so[w][k] * Wa[k * ACT + lane];
    } else if (lane == 21) {
        for (int k = 0; k < HID; k++)
            acc += so[w][k] * Wv[k];
    }
    float v = __shfl_sync(0xffffffffu, acc, 21);
    if (lane < ACT)
        outq[(size_t)row * ACT + lane] = acc + ba[lane] + v + bv[0];
}

__global__ void tail_copy_kernel(const float* __restrict__ c,
                                 const float* __restrict__ hT,
                                 float* __restrict__ out)
{
    int i = blockIdx.x * blockDim.x + threadIdx.x;
    if (i < B_DIM * HID) {
        out[i] = c[i];
        out[B_DIM * HID + i] = hT[i];
    }
}

// -----------------------------------------------------------------------------
extern "C" void kernel_launch(void* const* d_in, const int* in_sizes, int n_in,
                              void* d_out, int out_size)
{
    const float* c0    = (const float*)d_in[0];
    const float* h0    = (const float*)d_in[1];
    const float* obs   = (const float*)d_in[2];
    const void*  dones = d_in[3];
    const float* Wp1   = (const float*)d_in[4];
    const float* bp1   = (const float*)d_in[5];
    const float* Wp2   = (const float*)d_in[6];
    const float* bp2   = (const float*)d_in[7];
    const float* Wp3   = (const float*)d_in[8];
    const float* bp3   = (const float*)d_in[9];
    const float* Wpub  = (const float*)d_in[10];
    const float* bpub  = (const float*)d_in[11];
    const float* Wi    = (const float*)d_in[12];
    const float* Wh    = (const float*)d_in[13];
    const float* blstm = (const float*)d_in[14];
    const float* Wv    = (const float*)d_in[15];
    const float* bv    = (const float*)d_in[16];
    const float* Wa    = (const float*)d_in[17];
    const float* ba    = (const float*)d_in[18];
    float* out = (float*)d_out;

    float *priv1, *tmp, *publx, *xg, *hbuf, *cst, *gatesbuf;
    cudaGetSymbolAddress((void**)&priv1,    g_priv1);
    cudaGetSymbolAddress((void**)&tmp,      g_tmp);
    cudaGetSymbolAddress((void**)&publx,    g_publx);
    cudaGetSymbolAddress((void**)&xg,       g_xg);
    cudaGetSymbolAddress((void**)&hbuf,     g_h);
    cudaGetSymbolAddress((void**)&cst,      g_c);
    cudaGetSymbolAddress((void**)&gatesbuf, g_gates);

    dim3 blk(256);
    dim3 grid512(HID / BN, M_ROWS / BM);     // (4, 256)
    dim3 grid2048(GDIM / BN, M_ROWS / BM);   // (16, 256)

    // public path
    gemm_tf32<<<grid512, blk>>>(obs + PS, OBS_DIM, Wpub, HID, OBS_DIM - PS, bpub, publx, 1, nullptr);
    gemm_tf32<<<grid2048, blk>>>(publx,   HID,     Wi,   GDIM, HID,        nullptr, xg, 0, nullptr);
    // private path (ping-pong priv1 <-> tmp; final priv_o in priv1)
    gemm_tf32<<<grid512, blk>>>(obs,   OBS_DIM, Wp1, HID, PS,  bp1, tmp,   1, nullptr);
    gemm_tf32<<<grid512, blk>>>(tmp,   HID,     Wp2, HID, HID, bp2, publx, 1, nullptr);
    gemm_tf32<<<grid512, blk>>>(publx, HID,     Wp3, HID, HID, bp3, priv1, 1, nullptr);

    // LSTM scan
    dim3 lgrid(GDIM / BN, B_DIM / BM);   // (16, 2)
    for (int t = 0; t < T_DIM; t++) {
        const float* hp = (t == 0) ? h0 : (hbuf + (size_t)(t - 1) * B_DIM * HID);
        const void* dnt = (const void*)((const char*)dones + (size_t)t * B_DIM * 4);
        gemm_tf32<<<lgrid, blk>>>(hp, HID, Wh, GDIM, HID, nullptr, gatesbuf, 0, dnt);
        lstm_epilogue<<<(B_DIM * HID) / 256, 256>>>(
            gatesbuf, xg + (size_t)t * B_DIM * GDIM, blstm, dnt,
            (t == 0) ? c0 : cst, cst,
            hbuf + (size_t)t * B_DIM * HID);
    }

    // output layout
    const int STATE = B_DIM * HID;
    const int QSZ   = M_ROWS * ACT;
    float* qdst = out;
    int write_states = 0;
    if (out_size >= 2 * STATE + QSZ) { qdst = out + 2 * STATE; write_states = 1; }

    head_kernel<<<M_ROWS / 8, 256>>>(priv1, hbuf, Wv, bv, Wa, ba, qdst);

    if (write_states) {
        tail_copy_kernel<<<(STATE + 255) / 256, 256>>>(
            cst, hbuf + (size_t)(T_DIM - 1) * B_DIM * HID, out);
    }
}

// round 6
// speedup vs baseline: 2.3222x; 1.5057x over previous
#include <cuda_runtime.h>
#include <cuda_bf16.h>
#include <math.h>

// Problem dims
#define T_DIM 128
#define B_DIM 256
#define OBS_DIM 1024
#define PS 512
#define HID 512
#define GDIM 2048
#define ACT 21
#define M_ROWS (T_DIM * B_DIM)   // 32768

// ---------------- scratch ------------------------------------------------------
__device__ float g_priv1[M_ROWS * HID];   // priv_o (final, persists through head)
__device__ float g_tmp[M_ROWS * HID];     // priv intermediate
__device__ float g_publx[M_ROWS * HID];   // publ_x / priv intermediate 2
__device__ float g_xg[M_ROWS * GDIM];     // x_gates
__device__ float g_h[M_ROWS * HID];       // h at every t
__device__ float g_c[B_DIM * HID];        // c state

// dones as 32-bit words: nonzero <=> True (works for int32 and float32 bools)
#define DONE(p, idx) (((const unsigned int*)(p))[idx] != 0u)

// ---------------- tf32 mma helpers --------------------------------------------
__device__ __forceinline__ unsigned f2tf32(float x) {
    unsigned u;
    asm("cvt.rna.tf32.f32 %0, %1;" : "=r"(u) : "f"(x));
    return u;
}

__device__ __forceinline__ void mma_tf32(float* d, const unsigned* a, const unsigned* b) {
    asm volatile(
        "mma.sync.aligned.m16n8k8.row.col.f32.tf32.tf32.f32 "
        "{%0,%1,%2,%3}, {%4,%5,%6,%7}, {%8,%9}, {%0,%1,%2,%3};"
        : "+f"(d[0]), "+f"(d[1]), "+f"(d[2]), "+f"(d[3])
        : "r"(a[0]), "r"(a[1]), "r"(a[2]), "r"(a[3]),
          "r"(b[0]), "r"(b[1]));
}

// ---------------- tf32 GEMM: C = act(A @ W + bias) -----------------------------
// BM=128, BN=128, BK=32. 256 threads = 8 warps (2 m x 4 n), warp tile 64x32.
#define BM 128
#define BN 128
#define BK 32

__global__ __launch_bounds__(256) void gemm_tf32(
    const float* __restrict__ A, int lda,
    const float* __restrict__ W,      // K x N row-major
    int N, int K,
    const float* __restrict__ bias,
    float* __restrict__ C,
    int relu)
{
    __shared__ unsigned As[BM][36];   // [m][k]
    __shared__ unsigned Bs[BN][36];   // [n][k]

    const int tid  = threadIdx.x;
    const int warp = tid >> 5;
    const int lane = tid & 31;
    const int wm = warp >> 2;
    const int wn = warp & 3;
    const int row0 = blockIdx.y * BM;
    const int col0 = blockIdx.x * BN;
    const int q = lane >> 2;
    const int r = lane & 3;

    float acc[4][4][4];
#pragma unroll
    for (int mt = 0; mt < 4; mt++)
#pragma unroll
        for (int nt = 0; nt < 4; nt++)
#pragma unroll
            for (int e = 0; e < 4; e++) acc[mt][nt][e] = 0.f;

    for (int k0 = 0; k0 < K; k0 += BK) {
#pragma unroll
        for (int i = 0; i < 4; i++) {
            int lin = i * 256 + tid;
            int m   = lin >> 3;
            int k4  = (lin & 7) * 4;
            float4 v = *(const float4*)(A + (size_t)(row0 + m) * lda + k0 + k4);
            As[m][k4 + 0] = f2tf32(v.x);
            As[m][k4 + 1] = f2tf32(v.y);
            As[m][k4 + 2] = f2tf32(v.z);
            As[m][k4 + 3] = f2tf32(v.w);
        }
#pragma unroll
        for (int i = 0; i < 16; i++) {
            int idx = i * 8 + warp;
            int k = (idx & 7) * 4 + r;
            int n = (idx >> 3) * 8 + q;
            Bs[n][k] = f2tf32(W[(size_t)(k0 + k) * N + col0 + n]);
        }
        __syncthreads();

#pragma unroll
        for (int ks = 0; ks < 4; ks++) {
            unsigned af[4][4], bf[4][2];
            int c = ks * 8 + r;
#pragma unroll
            for (int mt = 0; mt < 4; mt++) {
                int rr = wm * 64 + mt * 16 + q;
                af[mt][0] = As[rr][c];
                af[mt][1] = As[rr + 8][c];
                af[mt][2] = As[rr][c + 4];
                af[mt][3] = As[rr + 8][c + 4];
            }
#pragma unroll
            for (int nt = 0; nt < 4; nt++) {
                int nn = wn * 32 + nt * 8 + q;
                bf[nt][0] = Bs[nn][c];
                bf[nt][1] = Bs[nn][c + 4];
            }
#pragma unroll
            for (int mt = 0; mt < 4; mt++)
#pragma unroll
                for (int nt = 0; nt < 4; nt++)
                    mma_tf32(acc[mt][nt], af[mt], bf[nt]);
        }
        __syncthreads();
    }

#pragma unroll
    for (int mt = 0; mt < 4; mt++) {
        int rbase = row0 + wm * 64 + mt * 16 + q;
#pragma unroll
        for (int nt = 0; nt < 4; nt++) {
            int cbase = col0 + wn * 32 + nt * 8 + 2 * r;
            float v0 = acc[mt][nt][0];
            float v1 = acc[mt][nt][1];
            float v2 = acc[mt][nt][2];
            float v3 = acc[mt][nt][3];
            if (bias) {
                float b0 = bias[cbase], b1 = bias[cbase + 1];
                v0 += b0; v1 += b1; v2 += b0; v3 += b1;
            }
            if (relu) {
                v0 = fmaxf(v0, 0.f); v1 = fmaxf(v1, 0.f);
                v2 = fmaxf(v2, 0.f); v3 = fmaxf(v3, 0.f);
            }
            C[(size_t)rbase * N + cbase]           = v0;
            C[(size_t)rbase * N + cbase + 1]       = v1;
            C[(size_t)(rbase + 8) * N + cbase]     = v2;
            C[(size_t)(rbase + 8) * N + cbase + 1] = v3;
        }
    }
}

// ---------------- fused LSTM step ---------------------------------------------
// Tile: 64 batch x 64 gate-cols (4 gates x 16 hid). Grid (32, 4) = 128 CTAs.
// gates = mask(h_prev) @ Wh (+xg +b fused), then LSTM pointwise in-kernel.
// Warp layout: 8 warps = 2m x 4n; warp wn covers exactly gate g = wn.
__global__ __launch_bounds__(256) void lstm_step_fused(
    const float* __restrict__ Wh,      // [512][2048]
    const float* __restrict__ xg,      // [B][2048] slice for this t
    const float* __restrict__ blstm,   // [2048]
    const void* __restrict__ dn,       // [B] bool words for this t
    const float* __restrict__ hprev,   // [B][512]
    const float* __restrict__ cin,     // [B][512]
    float* __restrict__ cout,          // [B][512]
    float* __restrict__ hout)          // [B][512]
{
    __shared__ char raw[2 * 64 * 36 * 4];                 // 18432 B
    unsigned (*As)[36] = (unsigned(*)[36])raw;            // [64][36]
    unsigned (*Bs)[36] = (unsigned(*)[36])(raw + 64 * 36 * 4);
    float (*gsm)[68] = (float(*)[68])raw;                 // [64][68] (17408 B)

    const int tid  = threadIdx.x;
    const int warp = tid >> 5;
    const int lane = tid & 31;
    const int wm = warp >> 2;        // 0..1
    const int wn = warp & 3;         // 0..3 == gate index
    const int q = lane >> 2;         // 0..7
    const int r = lane & 3;          // 0..3
    const int hid0 = blockIdx.x * 16;
    const int b0   = blockIdx.y * 64;

    float acc[2][2][4];
#pragma unroll
    for (int mt = 0; mt < 2; mt++)
#pragma unroll
        for (int nt = 0; nt < 2; nt++)
#pragma unroll
            for (int e = 0; e < 4; e++) acc[mt][nt][e] = 0.f;

    for (int k0 = 0; k0 < HID; k0 += 32) {
        // A tile: 64 x 32 of masked h_prev
#pragma unroll
        for (int i = 0; i < 2; i++) {
            int lin = i * 256 + tid;         // 0..511
            int m   = lin >> 3;              // 0..63
            int k4  = (lin & 7) * 4;
            int b   = b0 + m;
            float4 v = *(const float4*)(hprev + (size_t)b * HID + k0 + k4);
            if (DONE(dn, b)) v = make_float4(0.f, 0.f, 0.f, 0.f);
            As[m][k4 + 0] = f2tf32(v.x);
            As[m][k4 + 1] = f2tf32(v.y);
            As[m][k4 + 2] = f2tf32(v.z);
            As[m][k4 + 3] = f2tf32(v.w);
        }
        // B tile: 32k x 64n of Wh, gate-interleaved columns
#pragma unroll
        for (int i = 0; i < 8; i++) {
            int idx = i * 8 + warp;          // 0..63
            int k = (idx & 7) * 4 + r;
            int n = (idx >> 3) * 8 + q;      // 0..63
            int g = n >> 4, j = n & 15;
            int wcol = g * HID + hid0 + j;
            Bs[n][k] = f2tf32(Wh[(size_t)(k0 + k) * GDIM + wcol]);
        }
        __syncthreads();

#pragma unroll
        for (int ks = 0; ks < 4; ks++) {
            unsigned af[2][4], bf[2][2];
            int c = ks * 8 + r;
#pragma unroll
            for (int mt = 0; mt < 2; mt++) {
                int rr = wm * 32 + mt * 16 + q;
                af[mt][0] = As[rr][c];
                af[mt][1] = As[rr + 8][c];
                af[mt][2] = As[rr][c + 4];
                af[mt][3] = As[rr + 8][c + 4];
            }
#pragma unroll
            for (int nt = 0; nt < 2; nt++) {
                int nn = wn * 16 + nt * 8 + q;
                bf[nt][0] = Bs[nn][c];
                bf[nt][1] = Bs[nn][c + 4];
            }
#pragma unroll
            for (int mt = 0; mt < 2; mt++)
#pragma unroll
                for (int nt = 0; nt < 2; nt++)
                    mma_tf32(acc[mt][nt], af[mt], bf[nt]);
        }
        __syncthreads();
    }

    // Stage gates into smem, adding xg + b_lstm (warp wn = gate wn).
#pragma unroll
    for (int mt = 0; mt < 2; mt++) {
        int rl = wm * 32 + mt * 16 + q;          // local row
#pragma unroll
        for (int nt = 0; nt < 2; nt++) {
            int cl = wn * 16 + nt * 8 + 2 * r;   // local col
            int wcol = wn * HID + hid0 + nt * 8 + 2 * r;
            float2 bb = *(const float2*)(blstm + wcol);
            float2 x0 = *(const float2*)(xg + (size_t)(b0 + rl) * GDIM + wcol);
            float2 x1 = *(const float2*)(xg + (size_t)(b0 + rl + 8) * GDIM + wcol);
            gsm[rl][cl]         = acc[mt][nt][0] + x0.x + bb.x;
            gsm[rl][cl + 1]     = acc[mt][nt][1] + x0.y + bb.y;
            gsm[rl + 8][cl]     = acc[mt][nt][2] + x1.x + bb.x;
            gsm[rl + 8][cl + 1] = acc[mt][nt][3] + x1.y + bb.y;
        }
    }
    __syncthreads();

    // Pointwise LSTM update: 64 x 16 items, 4 per thread
#pragma unroll
    for (int it = 0; it < 4; it++) {
        int idx = it * 256 + tid;        // 0..1023
        int bl = idx >> 4, j = idx & 15;
        int b = b0 + bl, hid = hid0 + j;
        float iv = gsm[bl][j];
        float fv = gsm[bl][16 + j];
        float gv = gsm[bl][32 + j];
        float ov = gsm[bl][48 + j];
        float is = 1.f / (1.f + expf(-iv));
        float fs = 1.f / (1.f + expf(-fv));
        float os = 1.f / (1.f + expf(-ov));
        float gt = tanhf(gv);
        float cm = DONE(dn, b) ? 0.f : cin[(size_t)b * HID + hid];
        float nc = fs * cm + is * gt;
        cout[(size_t)b * HID + hid] = nc;
        hout[(size_t)b * HID + hid] = os * tanhf(nc);
    }
}

// ---------------- head ---------------------------------------------------------
__global__ __launch_bounds__(256) void head_kernel(
    const float* __restrict__ privo, const float* __restrict__ hbuf,
    const float* __restrict__ Wv, const float* __restrict__ bv,
    const float* __restrict__ Wa, const float* __restrict__ ba,
    float* __restrict__ outq)
{
    __shared__ float so[8][HID];
    const int tid = threadIdx.x;
    const int w = tid >> 5, lane = tid & 31;
    const int row = blockIdx.x * 8 + w;

    for (int k = lane; k < HID; k += 32)
        so[w][k] = privo[(size_t)row * HID + k] * hbuf[(size_t)row * HID + k];
    __syncwarp();

    float acc = 0.f;
    if (lane < 21) {
        for (int k = 0; k < HID; k++)
            acc += so[w][k] * Wa[k * ACT + lane];
    } else if (lane == 21) {
        for (int k = 0; k < HID; k++)
            acc += so[w][k] * Wv[k];
    }
    float v = __shfl_sync(0xffffffffu, acc, 21);
    if (lane < ACT)
        outq[(size_t)row * ACT + lane] = acc + ba[lane] + v + bv[0];
}

__global__ void tail_copy_kernel(const float* __restrict__ c,
                                 const float* __restrict__ hT,
                                 float* __restrict__ out)
{
    int i = blockIdx.x * blockDim.x + threadIdx.x;
    if (i < B_DIM * HID) {
        out[i] = c[i];
        out[B_DIM * HID + i] = hT[i];
    }
}

// -----------------------------------------------------------------------------
extern "C" void kernel_launch(void* const* d_in, const int* in_sizes, int n_in,
                              void* d_out, int out_size)
{
    const float* c0    = (const float*)d_in[0];
    const float* h0    = (const float*)d_in[1];
    const float* obs   = (const float*)d_in[2];
    const void*  dones = d_in[3];
    const float* Wp1   = (const float*)d_in[4];
    const float* bp1   = (const float*)d_in[5];
    const float* Wp2   = (const float*)d_in[6];
    const float* bp2   = (const float*)d_in[7];
    const float* Wp3   = (const float*)d_in[8];
    const float* bp3   = (const float*)d_in[9];
    const float* Wpub  = (const float*)d_in[10];
    const float* bpub  = (const float*)d_in[11];
    const float* Wi    = (const float*)d_in[12];
    const float* Wh    = (const float*)d_in[13];
    const float* blstm = (const float*)d_in[14];
    const float* Wv    = (const float*)d_in[15];
    const float* bv    = (const float*)d_in[16];
    const float* Wa    = (const float*)d_in[17];
    const float* ba    = (const float*)d_in[18];
    float* out = (float*)d_out;

    float *priv1, *tmp, *publx, *xg, *hbuf, *cst;
    cudaGetSymbolAddress((void**)&priv1, g_priv1);
    cudaGetSymbolAddress((void**)&tmp,   g_tmp);
    cudaGetSymbolAddress((void**)&publx, g_publx);
    cudaGetSymbolAddress((void**)&xg,    g_xg);
    cudaGetSymbolAddress((void**)&hbuf,  g_h);
    cudaGetSymbolAddress((void**)&cst,   g_c);

    dim3 blk(256);
    dim3 grid512(HID / BN, M_ROWS / BM);     // (4, 256)
    dim3 grid2048(GDIM / BN, M_ROWS / BM);   // (16, 256)

    // public path
    gemm_tf32<<<grid512, blk>>>(obs + PS, OBS_DIM, Wpub, HID, OBS_DIM - PS, bpub, publx, 1);
    gemm_tf32<<<grid2048, blk>>>(publx,   HID,     Wi,   GDIM, HID,        nullptr, xg, 0);
    // private path (final priv_o in priv1)
    gemm_tf32<<<grid512, blk>>>(obs,   OBS_DIM, Wp1, HID, PS,  bp1, tmp,   1);
    gemm_tf32<<<grid512, blk>>>(tmp,   HID,     Wp2, HID, HID, bp2, publx, 1);
    gemm_tf32<<<grid512, blk>>>(publx, HID,     Wp3, HID, HID, bp3, priv1, 1);

    // LSTM scan: one fused kernel per step
    dim3 lgrid(HID / 16, B_DIM / 64);        // (32, 4) = 128 CTAs
    for (int t = 0; t < T_DIM; t++) {
        const float* hp = (t == 0) ? h0 : (hbuf + (size_t)(t - 1) * B_DIM * HID);
        const void* dnt = (const void*)((const char*)dones + (size_t)t * B_DIM * 4);
        lstm_step_fused<<<lgrid, blk>>>(Wh,
                                        xg + (size_t)t * B_DIM * GDIM,
                                        blstm, dnt, hp,
                                        (t == 0) ? c0 : cst, cst,
                                        hbuf + (size_t)t * B_DIM * HID);
    }

    // output layout
    const int STATE = B_DIM * HID;
    const int QSZ   = M_ROWS * ACT;
    float* qdst = out;
    int write_states = 0;
    if (out_size >= 2 * STATE + QSZ) { qdst = out + 2 * STATE; write_states = 1; }

    head_kernel<<<M_ROWS / 8, 256>>>(priv1, hbuf, Wv, bv, Wa, ba, qdst);

    if (write_states) {
        tail_copy_kernel<<<(STATE + 255) / 256, 256>>>(
            cst, hbuf + (size_t)(T_DIM - 1) * B_DIM * HID, out);
    }
}

// round 7
// speedup vs baseline: 3.5760x; 1.5399x over previous
#include <cuda_runtime.h>
#include <cuda_bf16.h>
#include <math.h>

// Problem dims
#define T_DIM 128
#define B_DIM 256
#define OBS_DIM 1024
#define PS 512
#define HID 512
#define GDIM 2048
#define ACT 21
#define M_ROWS (T_DIM * B_DIM)   // 32768
#define NCTA 128                 // persistent scan grid size (must be <= #SMs)

// ---------------- scratch ------------------------------------------------------
__device__ float g_priv1[M_ROWS * HID];   // priv_o (final, persists through head)
__device__ float g_tmp[M_ROWS * HID];     // priv intermediate
__device__ float g_publx[M_ROWS * HID];   // publ_x / priv intermediate 2
__device__ float g_xg[M_ROWS * GDIM];     // x_gates
__device__ float g_h[M_ROWS * HID];       // h at every t
__device__ float g_c[B_DIM * HID];        // c state (final)
__device__ int   g_bar[T_DIM];            // scan barrier counters

// dones as 32-bit words: nonzero <=> True (works for int32 and float32 bools)
#define DONE(p, idx) (((const unsigned int*)(p))[idx] != 0u)

// ---------------- tf32 mma helpers --------------------------------------------
__device__ __forceinline__ unsigned f2tf32(float x) {
    unsigned u;
    asm("cvt.rna.tf32.f32 %0, %1;" : "=r"(u) : "f"(x));
    return u;
}

__device__ __forceinline__ void mma_tf32(float* d, const unsigned* a, const unsigned* b) {
    asm volatile(
        "mma.sync.aligned.m16n8k8.row.col.f32.tf32.tf32.f32 "
        "{%0,%1,%2,%3}, {%4,%5,%6,%7}, {%8,%9}, {%0,%1,%2,%3};"
        : "+f"(d[0]), "+f"(d[1]), "+f"(d[2]), "+f"(d[3])
        : "r"(a[0]), "r"(a[1]), "r"(a[2]), "r"(a[3]),
          "r"(b[0]), "r"(b[1]));
}

// ---------------- tf32 GEMM: C = act(A @ W + bias) -----------------------------
// BM=128, BN=128, BK=32. 256 threads = 8 warps (2 m x 4 n), warp tile 64x32.
#define BM 128
#define BN 128
#define BK 32

__global__ __launch_bounds__(256) void gemm_tf32(
    const float* __restrict__ A, int lda,
    const float* __restrict__ W,      // K x N row-major
    int N, int K,
    const float* __restrict__ bias,
    float* __restrict__ C,
    int relu)
{
    __shared__ unsigned As[BM][36];   // [m][k]
    __shared__ unsigned Bs[BN][36];   // [n][k]

    const int tid  = threadIdx.x;
    const int warp = tid >> 5;
    const int lane = tid & 31;
    const int wm = warp >> 2;
    const int wn = warp & 3;
    const int row0 = blockIdx.y * BM;
    const int col0 = blockIdx.x * BN;
    const int q = lane >> 2;
    const int r = lane & 3;

    float acc[4][4][4];
#pragma unroll
    for (int mt = 0; mt < 4; mt++)
#pragma unroll
        for (int nt = 0; nt < 4; nt++)
#pragma unroll
            for (int e = 0; e < 4; e++) acc[mt][nt][e] = 0.f;

    for (int k0 = 0; k0 < K; k0 += BK) {
#pragma unroll
        for (int i = 0; i < 4; i++) {
            int lin = i * 256 + tid;
            int m   = lin >> 3;
            int k4  = (lin & 7) * 4;
            float4 v = *(const float4*)(A + (size_t)(row0 + m) * lda + k0 + k4);
            As[m][k4 + 0] = f2tf32(v.x);
            As[m][k4 + 1] = f2tf32(v.y);
            As[m][k4 + 2] = f2tf32(v.z);
            As[m][k4 + 3] = f2tf32(v.w);
        }
#pragma unroll
        for (int i = 0; i < 16; i++) {
            int idx = i * 8 + warp;
            int k = (idx & 7) * 4 + r;
            int n = (idx >> 3) * 8 + q;
            Bs[n][k] = f2tf32(W[(size_t)(k0 + k) * N + col0 + n]);
        }
        __syncthreads();

#pragma unroll
        for (int ks = 0; ks < 4; ks++) {
            unsigned af[4][4], bf[4][2];
            int c = ks * 8 + r;
#pragma unroll
            for (int mt = 0; mt < 4; mt++) {
                int rr = wm * 64 + mt * 16 + q;
                af[mt][0] = As[rr][c];
                af[mt][1] = As[rr + 8][c];
                af[mt][2] = As[rr][c + 4];
                af[mt][3] = As[rr + 8][c + 4];
            }
#pragma unroll
            for (int nt = 0; nt < 4; nt++) {
                int nn = wn * 32 + nt * 8 + q;
                bf[nt][0] = Bs[nn][c];
                bf[nt][1] = Bs[nn][c + 4];
            }
#pragma unroll
            for (int mt = 0; mt < 4; mt++)
#pragma unroll
                for (int nt = 0; nt < 4; nt++)
                    mma_tf32(acc[mt][nt], af[mt], bf[nt]);
        }
        __syncthreads();
    }

#pragma unroll
    for (int mt = 0; mt < 4; mt++) {
        int rbase = row0 + wm * 64 + mt * 16 + q;
#pragma unroll
        for (int nt = 0; nt < 4; nt++) {
            int cbase = col0 + wn * 32 + nt * 8 + 2 * r;
            float v0 = acc[mt][nt][0];
            float v1 = acc[mt][nt][1];
            float v2 = acc[mt][nt][2];
            float v3 = acc[mt][nt][3];
            if (bias) {
                float b0 = bias[cbase], b1 = bias[cbase + 1];
                v0 += b0; v1 += b1; v2 += b0; v3 += b1;
            }
            if (relu) {
                v0 = fmaxf(v0, 0.f); v1 = fmaxf(v1, 0.f);
                v2 = fmaxf(v2, 0.f); v3 = fmaxf(v3, 0.f);
            }
            C[(size_t)rbase * N + cbase]           = v0;
            C[(size_t)rbase * N + cbase + 1]       = v1;
            C[(size_t)(rbase + 8) * N + cbase]     = v2;
            C[(size_t)(rbase + 8) * N + cbase + 1] = v3;
        }
    }
}

// ---------------- persistent LSTM scan -----------------------------------------
// 128 CTAs (32 hid-blocks x 4 batch-blocks), all co-resident (1 CTA/SM).
// Per CTA: Wh slice [512][64 gate-cols] lives in smem as tf32 for all 128 steps.
// c state lives in registers (each (b,hid) owned by one thread). h goes through
// global hbuf each step, with an atomic-counter grid barrier between steps.
// Dyn smem: WhS 16*64*36*4 = 147456 B ; As double buffer 2*64*36*4 = 18432 B
// (gsm [64][68] floats aliases the As region). Total 165888 B.
#define SCAN_SMEM (147456 + 18432)

__global__ void bar_reset_kernel() {
    if (threadIdx.x < T_DIM) g_bar[threadIdx.x] = 0;
}

__global__ __launch_bounds__(256, 1) void lstm_scan(
    const float* __restrict__ Wh,      // [512][2048]
    const float* __restrict__ xg,      // [T][B][2048]
    const float* __restrict__ blstm,   // [2048]
    const void* __restrict__ dones,    // [T][B] bool words
    const float* __restrict__ h0,      // [B][512]
    const float* __restrict__ c0,      // [B][512]
    float* __restrict__ hbuf,          // [T][B][512]
    float* __restrict__ cst)           // [B][512]
{
    extern __shared__ char dsm[];
    unsigned (*WhS)[64][36] = (unsigned(*)[64][36])dsm;             // [16][64][36]
    unsigned (*As)[64][36]  = (unsigned(*)[64][36])(dsm + 147456);  // [2][64][36]
    float (*gsm)[68]        = (float(*)[68])(dsm + 147456);         // aliases As

    const int tid  = threadIdx.x;
    const int warp = tid >> 5;
    const int lane = tid & 31;
    const int wm = warp >> 2;        // 0..1
    const int wn = warp & 3;         // 0..3 == gate index
    const int q = lane >> 2;         // 0..7
    const int r = lane & 3;          // 0..3
    const int hid0 = blockIdx.x * 16;
    const int b0   = blockIdx.y * 64;

    // ---- load this CTA's Wh slice into smem (tf32), gate-interleaved cols ----
#pragma unroll 4
    for (int kk = 0; kk < 16; kk++) {
#pragma unroll
        for (int i = 0; i < 8; i++) {
            int idx = i * 8 + warp;          // 0..63
            int k = (idx & 7) * 4 + r;       // 0..31
            int n = (idx >> 3) * 8 + q;      // 0..63
            int wcol = (n >> 4) * HID + hid0 + (n & 15);
            WhS[kk][n][k] = f2tf32(Wh[(size_t)(kk * 32 + k) * GDIM + wcol]);
        }
    }

    // ---- c state in registers: thread owns 4 (b,hid) cells, fixed mapping ----
    float c_reg[4];
#pragma unroll
    for (int it = 0; it < 4; it++) {
        int idx = it * 256 + tid;
        int bl = idx >> 4, j = idx & 15;
        c_reg[it] = c0[(size_t)(b0 + bl) * HID + hid0 + j];
    }
    __syncthreads();

    // A-tile prefetch registers (2 float4 per thread)
    const int lm0 = tid >> 3;              // row for i=0 chunk (0..31)
    const int lk4 = (tid & 7) * 4;         // k offset

    for (int t = 0; t < T_DIM; t++) {
        const float* hp = t ? (hbuf + (size_t)(t - 1) * B_DIM * HID) : h0;
        const unsigned* dn = (const unsigned*)dones + (size_t)t * B_DIM;
        const float* xgt = xg + (size_t)t * B_DIM * GDIM;

        float acc[2][2][4];
#pragma unroll
        for (int mt = 0; mt < 2; mt++)
#pragma unroll
            for (int nt = 0; nt < 2; nt++)
#pragma unroll
                for (int e = 0; e < 4; e++) acc[mt][nt][e] = 0.f;

        // prefetch tile 0
        float4 av0, av1;
        av0 = *(const float4*)(hp + (size_t)(b0 + lm0) * HID + lk4);
        av1 = *(const float4*)(hp + (size_t)(b0 + 32 + lm0) * HID + lk4);
        if (dn[b0 + lm0] != 0u)      av0 = make_float4(0.f, 0.f, 0.f, 0.f);
        if (dn[b0 + 32 + lm0] != 0u) av1 = make_float4(0.f, 0.f, 0.f, 0.f);
        As[0][lm0][lk4 + 0] = f2tf32(av0.x);
        As[0][lm0][lk4 + 1] = f2tf32(av0.y);
        As[0][lm0][lk4 + 2] = f2tf32(av0.z);
        As[0][lm0][lk4 + 3] = f2tf32(av0.w);
        As[0][32 + lm0][lk4 + 0] = f2tf32(av1.x);
        As[0][32 + lm0][lk4 + 1] = f2tf32(av1.y);
        As[0][32 + lm0][lk4 + 2] = f2tf32(av1.z);
        As[0][32 + lm0][lk4 + 3] = f2tf32(av1.w);

#pragma unroll
        for (int kk = 0; kk < 16; kk++) {
            __syncthreads();
            if (kk < 15) {
                int k0 = (kk + 1) * 32;
                av0 = *(const float4*)(hp + (size_t)(b0 + lm0) * HID + k0 + lk4);
                av1 = *(const float4*)(hp + (size_t)(b0 + 32 + lm0) * HID + k0 + lk4);
            }
            const int cur = kk & 1;
#pragma unroll
            for (int ks = 0; ks < 4; ks++) {
                unsigned af[2][4], bf[2][2];
                int c = ks * 8 + r;
#pragma unroll
                for (int mt = 0; mt < 2; mt++) {
                    int rr = wm * 32 + mt * 16 + q;
                    af[mt][0] = As[cur][rr][c];
                    af[mt][1] = As[cur][rr + 8][c];
                    af[mt][2] = As[cur][rr][c + 4];
                    af[mt][3] = As[cur][rr + 8][c + 4];
                }
#pragma unroll
                for (int nt = 0; nt < 2; nt++) {
                    int nn = wn * 16 + nt * 8 + q;
                    bf[nt][0] = WhS[kk][nn][c];
                    bf[nt][1] = WhS[kk][nn][c + 4];
                }
#pragma unroll
                for (int mt = 0; mt < 2; mt++)
#pragma unroll
                    for (int nt = 0; nt < 2; nt++)
                        mma_tf32(acc[mt][nt], af[mt], bf[nt]);
            }
            if (kk < 15) {
                const int nxt = cur ^ 1;
                if (dn[b0 + lm0] != 0u)      av0 = make_float4(0.f, 0.f, 0.f, 0.f);
                if (dn[b0 + 32 + lm0] != 0u) av1 = make_float4(0.f, 0.f, 0.f, 0.f);
                As[nxt][lm0][lk4 + 0] = f2tf32(av0.x);
                As[nxt][lm0][lk4 + 1] = f2tf32(av0.y);
                As[nxt][lm0][lk4 + 2] = f2tf32(av0.z);
                As[nxt][lm0][lk4 + 3] = f2tf32(av0.w);
                As[nxt][32 + lm0][lk4 + 0] = f2tf32(av1.x);
                As[nxt][32 + lm0][lk4 + 1] = f2tf32(av1.y);
                As[nxt][32 + lm0][lk4 + 2] = f2tf32(av1.z);
                As[nxt][32 + lm0][lk4 + 3] = f2tf32(av1.w);
            }
        }
        __syncthreads();   // all compute done before gsm (aliases As) is written

        // ---- stage gates into smem, adding xg + b_lstm (warp wn = gate wn) ----
#pragma unroll
        for (int mt = 0; mt < 2; mt++) {
            int rl = wm * 32 + mt * 16 + q;
#pragma unroll
            for (int nt = 0; nt < 2; nt++) {
                int cl = wn * 16 + nt * 8 + 2 * r;
                int wcol = wn * HID + hid0 + nt * 8 + 2 * r;
                float2 bb = *(const float2*)(blstm + wcol);
                float2 x0 = *(const float2*)(xgt + (size_t)(b0 + rl) * GDIM + wcol);
                float2 x1 = *(const float2*)(xgt + (size_t)(b0 + rl + 8) * GDIM + wcol);
                gsm[rl][cl]         = acc[mt][nt][0] + x0.x + bb.x;
                gsm[rl][cl + 1]     = acc[mt][nt][1] + x0.y + bb.y;
                gsm[rl + 8][cl]     = acc[mt][nt][2] + x1.x + bb.x;
                gsm[rl + 8][cl + 1] = acc[mt][nt][3] + x1.y + bb.y;
            }
        }
        __syncthreads();

        // ---- pointwise LSTM update (c in registers) ----
        float* hout = hbuf + (size_t)t * B_DIM * HID;
#pragma unroll
        for (int it = 0; it < 4; it++) {
            int idx = it * 256 + tid;
            int bl = idx >> 4, j = idx & 15;
            int b = b0 + bl, hid = hid0 + j;
            float iv = gsm[bl][j];
            float fv = gsm[bl][16 + j];
            float gv = gsm[bl][32 + j];
            float ov = gsm[bl][48 + j];
            float is = 1.f / (1.f + expf(-iv));
            float fs = 1.f / (1.f + expf(-fv));
            float os = 1.f / (1.f + expf(-ov));
            float gt = tanhf(gv);
            float cm = (dn[b] != 0u) ? 0.f : c_reg[it];
            float nc = fs * cm + is * gt;
            c_reg[it] = nc;
            hout[(size_t)b * HID + hid] = os * tanhf(nc);
            if (t == T_DIM - 1)
                cst[(size_t)b * HID + hid] = nc;
        }

        // ---- grid barrier between steps ----
        if (t < T_DIM - 1) {
            __threadfence();
            __syncthreads();                 // all threads done (h written, gsm read)
            if (tid == 0) {
                atomicAdd(&g_bar[t], 1);
                while (*(volatile int*)&g_bar[t] < NCTA) { }
            }
            __syncthreads();                 // release; h of step t visible
        }
    }
}

// ---------------- head ---------------------------------------------------------
__global__ __launch_bounds__(256) void head_kernel(
    const float* __restrict__ privo, const float* __restrict__ hbuf,
    const float* __restrict__ Wv, const float* __restrict__ bv,
    const float* __restrict__ Wa, const float* __restrict__ ba,
    float* __restrict__ outq)
{
    __shared__ float so[8][HID];
    const int tid = threadIdx.x;
    const int w = tid >> 5, lane = tid & 31;
    const int row = blockIdx.x * 8 + w;

    for (int k = lane; k < HID; k += 32)
        so[w][k] = privo[(size_t)row * HID + k] * hbuf[(size_t)row * HID + k];
    __syncwarp();

    float acc = 0.f;
    if (lane < 21) {
        for (int k = 0; k < HID; k++)
            acc += so[w][k] * Wa[k * ACT + lane];
    } else if (lane == 21) {
        for (int k = 0; k < HID; k++)
            acc += so[w][k] * Wv[k];
    }
    float v = __shfl_sync(0xffffffffu, acc, 21);
    if (lane < ACT)
        outq[(size_t)row * ACT + lane] = acc + ba[lane] + v + bv[0];
}

__global__ void tail_copy_kernel(const float* __restrict__ c,
                                 const float* __restrict__ hT,
                                 float* __restrict__ out)
{
    int i = blockIdx.x * blockDim.x + threadIdx.x;
    if (i < B_DIM * HID) {
        out[i] = c[i];
        out[B_DIM * HID + i] = hT[i];
    }
}

// -----------------------------------------------------------------------------
extern "C" void kernel_launch(void* const* d_in, const int* in_sizes, int n_in,
                              void* d_out, int out_size)
{
    const float* c0    = (const float*)d_in[0];
    const float* h0    = (const float*)d_in[1];
    const float* obs   = (const float*)d_in[2];
    const void*  dones = d_in[3];
    const float* Wp1   = (const float*)d_in[4];
    const float* bp1   = (const float*)d_in[5];
    const float* Wp2   = (const float*)d_in[6];
    const float* bp2   = (const float*)d_in[7];
    const float* Wp3   = (const float*)d_in[8];
    const float* bp3   = (const float*)d_in[9];
    const float* Wpub  = (const float*)d_in[10];
    const float* bpub  = (const float*)d_in[11];
    const float* Wi    = (const float*)d_in[12];
    const float* Wh    = (const float*)d_in[13];
    const float* blstm = (const float*)d_in[14];
    const float* Wv    = (const float*)d_in[15];
    const float* bv    = (const float*)d_in[16];
    const float* Wa    = (const float*)d_in[17];
    const float* ba    = (const float*)d_in[18];
    float* out = (float*)d_out;

    float *priv1, *tmp, *publx, *xg, *hbuf, *cst;
    cudaGetSymbolAddress((void**)&priv1, g_priv1);
    cudaGetSymbolAddress((void**)&tmp,   g_tmp);
    cudaGetSymbolAddress((void**)&publx, g_publx);
    cudaGetSymbolAddress((void**)&xg,    g_xg);
    cudaGetSymbolAddress((void**)&hbuf,  g_h);
    cudaGetSymbolAddress((void**)&cst,   g_c);

    static int smem_set = 0;
    if (!smem_set) {
        cudaFuncSetAttribute(lstm_scan,
                             cudaFuncAttributeMaxDynamicSharedMemorySize,
                             SCAN_SMEM);
        smem_set = 1;
    }

    dim3 blk(256);
    dim3 grid512(HID / BN, M_ROWS / BM);     // (4, 256)
    dim3 grid2048(GDIM / BN, M_ROWS / BM);   // (16, 256)

    // public path
    gemm_tf32<<<grid512, blk>>>(obs + PS, OBS_DIM, Wpub, HID, OBS_DIM - PS, bpub, publx, 1);
    gemm_tf32<<<grid2048, blk>>>(publx,   HID,     Wi,   GDIM, HID,        nullptr, xg, 0);
    // private path (final priv_o in priv1)
    gemm_tf32<<<grid512, blk>>>(obs,   OBS_DIM, Wp1, HID, PS,  bp1, tmp,   1);
    gemm_tf32<<<grid512, blk>>>(tmp,   HID,     Wp2, HID, HID, bp2, publx, 1);
    gemm_tf32<<<grid512, blk>>>(publx, HID,     Wp3, HID, HID, bp3, priv1, 1);

    // LSTM scan: single persistent kernel, barrier counters reset each replay
    bar_reset_kernel<<<1, 128>>>();
    lstm_scan<<<dim3(32, 4), blk, SCAN_SMEM>>>(Wh, xg, blstm, dones, h0, c0,
                                               hbuf, cst);

    // output layout
    const int STATE = B_DIM * HID;
    const int QSZ   = M_ROWS * ACT;
    float* qdst = out;
    int write_states = 0;
    if (out_size >= 2 * STATE + QSZ) { qdst = out + 2 * STATE; write_states = 1; }

    head_kernel<<<M_ROWS / 8, 256>>>(priv1, hbuf, Wv, bv, Wa, ba, qdst);

    if (write_states) {
        tail_copy_kernel<<<(STATE + 255) / 256, 256>>>(
            cst, hbuf + (size_t)(T_DIM - 1) * B_DIM * HID, out);
    }
}